// round 10
// baseline (speedup 1.0000x reference)
#include <cuda_runtime.h>
#include <math.h>

#define DIMC   256
#define HEADS  8
#define HD     32
#define WINSZ  64
#define SHIFTN 32
#define HIDDEN 1024
#define BATCH  8
#define SEQ    16384
#define NTOK   (BATCH*SEQ)      /* 131072 */
#define NWIN   (NTOK/WINSZ)     /* 2048 */

/* ---------------- scratch (device globals: allocation-free) -------------- */
__device__ float g_shifted[NTOK*DIMC];
__device__ float g_qkv   [NTOK*3*DIMC];
__device__ float g_attn  [NTOK*DIMC];
__device__ float g_x1    [NTOK*DIMC];
__device__ float g_hn    [NTOK*DIMC];
__device__ float g_hidden[NTOK*HIDDEN];

/* ---------------- packed f32x2 helpers (sm_103a FFMA2) ------------------- */
__device__ __forceinline__ void ffma2(unsigned long long& d,
                                      unsigned long long a,
                                      unsigned long long b) {
    asm("fma.rn.f32x2 %0, %1, %2, %3;" : "=l"(d) : "l"(a), "l"(b), "l"(d));
}
__device__ __forceinline__ void unpack2(unsigned long long v, float& lo, float& hi) {
    asm("mov.b64 {%0, %1}, %2;" : "=f"(lo), "=f"(hi) : "l"(v));
}

/* ---------------- LayerNorm (warp per 256-float row) --------------------- */
/* shifted=1: out[row] = LN(x[row+SHIFT]) for ls < SEQ-SHIFT else 0 (fused shift) */
__global__ void ln_kernel(const float* __restrict__ xin, const float* __restrict__ g,
                          const float* __restrict__ b, float* __restrict__ out, int shifted)
{
    int gw   = (blockIdx.x * blockDim.x + threadIdx.x) >> 5;
    int lane = threadIdx.x & 31;
    if (gw >= NTOK) return;

    float4* o4 = reinterpret_cast<float4*>(out + (size_t)gw * DIMC);
    const float* src;
    if (shifted) {
        int ls = gw & (SEQ - 1);
        if (ls >= SEQ - SHIFTN) {
            float4 z = make_float4(0.f, 0.f, 0.f, 0.f);
            o4[lane] = z; o4[lane + 32] = z;
            return;
        }
        src = xin + ((size_t)gw + SHIFTN) * DIMC;   /* same batch: ls+SHIFT < SEQ */
    } else {
        src = xin + (size_t)gw * DIMC;
    }

    const float4* x4 = reinterpret_cast<const float4*>(src);
    float4 v0 = x4[lane], v1 = x4[lane + 32];
    float s  = v0.x + v0.y + v0.z + v0.w + v1.x + v1.y + v1.z + v1.w;
    float sq = v0.x*v0.x + v0.y*v0.y + v0.z*v0.z + v0.w*v0.w
             + v1.x*v1.x + v1.y*v1.y + v1.z*v1.z + v1.w*v1.w;
#pragma unroll
    for (int o = 16; o > 0; o >>= 1) {
        s  += __shfl_xor_sync(0xffffffffu, s,  o);
        sq += __shfl_xor_sync(0xffffffffu, sq, o);
    }
    float mu  = s * (1.0f / DIMC);
    float var = sq * (1.0f / DIMC) - mu * mu;
    float inv = rsqrtf(var + 1e-5f);

    const float4* g4 = reinterpret_cast<const float4*>(g);
    const float4* b4 = reinterpret_cast<const float4*>(b);
    float4 ga = g4[lane], gb = g4[lane + 32];
    float4 ba = b4[lane], bb = b4[lane + 32];
    float4 r0, r1;
    r0.x = (v0.x - mu) * inv * ga.x + ba.x;
    r0.y = (v0.y - mu) * inv * ga.y + ba.y;
    r0.z = (v0.z - mu) * inv * ga.z + ba.z;
    r0.w = (v0.w - mu) * inv * ga.w + ba.w;
    r1.x = (v1.x - mu) * inv * gb.x + bb.x;
    r1.y = (v1.y - mu) * inv * gb.y + bb.y;
    r1.z = (v1.z - mu) * inv * gb.z + bb.z;
    r1.w = (v1.w - mu) * inv * gb.w + bb.w;
    o4[lane] = r0; o4[lane + 32] = r1;
}

/* ------- 128x128x8 SGEMM, 8x8 microtile via f32x2 FFMA2, dbl-buffered ----
   A tile stored PRE-DUPLICATED as float2 (a,a); B pairs read directly from
   shared as 64-bit packed operands. Inner loop: 6 LDS.128 + 32 FFMA2, 0 MOVs.
   C[M,N] = A[M,K] @ B[K,N] + bias ; MODE: 0 plain, 1 +GELU(exact),
   2 proj: write C[(m+SHIFT)] = resid[(m+SHIFT)] + y (skip tail rows),
   3 +resid[m] */
#define BM 128
#define BN 128
#define BK 8

template <int MODE>
__global__ void __launch_bounds__(256)
gemm_kernel(const float* __restrict__ A, const float* __restrict__ Bw,
            const float* __restrict__ bias, float* __restrict__ C,
            const float* __restrict__ resid, int Ncols, int K)
{
    __shared__ float2 As2[2][BK][BM];     /* duplicated pairs: 8KB per buffer */
    __shared__ float  Bs [2][BK][BN];     /* 4KB per buffer */

    const int tid = threadIdx.x;
    const int m0 = blockIdx.y * BM;
    const int n0 = blockIdx.x * BN;
    const int tx = tid & 15;          /* 0..15 : column group */
    const int ty = tid >> 4;          /* 0..15 : row group    */

    /* global-load mapping: one float4 of A, one float4 of B per thread */
    const int a_row = tid >> 1;              /* 0..127 */
    const int a_kc  = (tid & 1) << 2;        /* 0 or 4 */
    const int b_row = tid >> 5;              /* 0..7   */
    const int b_col = (tid & 31) << 2;       /* 0..124 */

    const float* Ap = A + (size_t)(m0 + a_row) * K + a_kc;
    const float* Bp = Bw + (size_t)b_row * Ncols + n0 + b_col;

    /* acc2[i][j2] packs columns (2*j2, 2*j2+1) for row i */
    unsigned long long acc2[8][4];
#pragma unroll
    for (int i = 0; i < 8; i++)
#pragma unroll
        for (int j = 0; j < 4; j++) acc2[i][j] = 0ull;

    /* prologue: load first K-slab */
    float4 a_reg = *reinterpret_cast<const float4*>(Ap);
    float4 b_reg = *reinterpret_cast<const float4*>(Bp);
    As2[0][a_kc + 0][a_row] = make_float2(a_reg.x, a_reg.x);
    As2[0][a_kc + 1][a_row] = make_float2(a_reg.y, a_reg.y);
    As2[0][a_kc + 2][a_row] = make_float2(a_reg.z, a_reg.z);
    As2[0][a_kc + 3][a_row] = make_float2(a_reg.w, a_reg.w);
    *reinterpret_cast<float4*>(&Bs[0][b_row][b_col]) = b_reg;
    __syncthreads();

    int buf = 0;
    for (int k0 = BK; k0 < K; k0 += BK) {
        /* prefetch next slab into registers (overlaps with math below) */
        a_reg = *reinterpret_cast<const float4*>(Ap + k0);
        b_reg = *reinterpret_cast<const float4*>(Bp + (size_t)k0 * Ncols);

#pragma unroll
        for (int k = 0; k < BK; k++) {
            const unsigned long long* ap =
                reinterpret_cast<const unsigned long long*>(&As2[buf][k][ty * 8]);
            const unsigned long long* bq =
                reinterpret_cast<const unsigned long long*>(&Bs[buf][k][tx * 8]);
            unsigned long long bp0 = bq[0], bp1 = bq[1], bp2 = bq[2], bp3 = bq[3];
#pragma unroll
            for (int i = 0; i < 8; i++) {
                unsigned long long ad = ap[i];
                ffma2(acc2[i][0], ad, bp0);
                ffma2(acc2[i][1], ad, bp1);
                ffma2(acc2[i][2], ad, bp2);
                ffma2(acc2[i][3], ad, bp3);
            }
        }

        /* commit prefetched slab to the other buffer */
        int nb = buf ^ 1;
        As2[nb][a_kc + 0][a_row] = make_float2(a_reg.x, a_reg.x);
        As2[nb][a_kc + 1][a_row] = make_float2(a_reg.y, a_reg.y);
        As2[nb][a_kc + 2][a_row] = make_float2(a_reg.z, a_reg.z);
        As2[nb][a_kc + 3][a_row] = make_float2(a_reg.w, a_reg.w);
        *reinterpret_cast<float4*>(&Bs[nb][b_row][b_col]) = b_reg;
        __syncthreads();
        buf = nb;
    }

    /* final slab */
#pragma unroll
    for (int k = 0; k < BK; k++) {
        const unsigned long long* ap =
            reinterpret_cast<const unsigned long long*>(&As2[buf][k][ty * 8]);
        const unsigned long long* bq =
            reinterpret_cast<const unsigned long long*>(&Bs[buf][k][tx * 8]);
        unsigned long long bp0 = bq[0], bp1 = bq[1], bp2 = bq[2], bp3 = bq[3];
#pragma unroll
        for (int i = 0; i < 8; i++) {
            unsigned long long ad = ap[i];
            ffma2(acc2[i][0], ad, bp0);
            ffma2(acc2[i][1], ad, bp1);
            ffma2(acc2[i][2], ad, bp2);
            ffma2(acc2[i][3], ad, bp3);
        }
    }

    /* unpack to scalar grid */
    float acc[8][8];
#pragma unroll
    for (int i = 0; i < 8; i++)
#pragma unroll
        for (int j2 = 0; j2 < 4; j2++)
            unpack2(acc2[i][j2], acc[i][2 * j2], acc[i][2 * j2 + 1]);

    /* ------------- epilogue ------------- */
    const int n = n0 + tx * 8;
    float4 bv0 = *reinterpret_cast<const float4*>(&bias[n]);
    float4 bv1 = *reinterpret_cast<const float4*>(&bias[n + 4]);
#pragma unroll
    for (int i = 0; i < 8; i++) {
        int m = m0 + ty * 8 + i;
        float4 r0, r1;
        r0.x = acc[i][0] + bv0.x; r0.y = acc[i][1] + bv0.y;
        r0.z = acc[i][2] + bv0.z; r0.w = acc[i][3] + bv0.w;
        r1.x = acc[i][4] + bv1.x; r1.y = acc[i][5] + bv1.y;
        r1.z = acc[i][6] + bv1.z; r1.w = acc[i][7] + bv1.w;
        if (MODE == 1) {
            const float c = 0.70710678118654752f;
            r0.x = 0.5f * r0.x * (1.0f + erff(r0.x * c));
            r0.y = 0.5f * r0.y * (1.0f + erff(r0.y * c));
            r0.z = 0.5f * r0.z * (1.0f + erff(r0.z * c));
            r0.w = 0.5f * r0.w * (1.0f + erff(r0.w * c));
            r1.x = 0.5f * r1.x * (1.0f + erff(r1.x * c));
            r1.y = 0.5f * r1.y * (1.0f + erff(r1.y * c));
            r1.z = 0.5f * r1.z * (1.0f + erff(r1.z * c));
            r1.w = 0.5f * r1.w * (1.0f + erff(r1.w * c));
        }
        if (MODE == 2) {
            int ls = m & (SEQ - 1);
            if (ls >= SEQ - SHIFTN) continue;   /* rolled-off rows discarded */
            int dst = m + SHIFTN;               /* same batch */
            const float* rp = &resid[(size_t)dst * Ncols + n];
            float4 rv0 = *reinterpret_cast<const float4*>(rp);
            float4 rv1 = *reinterpret_cast<const float4*>(rp + 4);
            r0.x += rv0.x; r0.y += rv0.y; r0.z += rv0.z; r0.w += rv0.w;
            r1.x += rv1.x; r1.y += rv1.y; r1.z += rv1.z; r1.w += rv1.w;
            float* cp = &C[(size_t)dst * Ncols + n];
            *reinterpret_cast<float4*>(cp) = r0;
            *reinterpret_cast<float4*>(cp + 4) = r1;
            continue;
        }
        if (MODE == 3) {
            const float* rp = &resid[(size_t)m * Ncols + n];
            float4 rv0 = *reinterpret_cast<const float4*>(rp);
            float4 rv1 = *reinterpret_cast<const float4*>(rp + 4);
            r0.x += rv0.x; r0.y += rv0.y; r0.z += rv0.z; r0.w += rv0.w;
            r1.x += rv1.x; r1.y += rv1.y; r1.z += rv1.z; r1.w += rv1.w;
        }
        float* cp = &C[(size_t)m * Ncols + n];
        *reinterpret_cast<float4*>(cp) = r0;
        *reinterpret_cast<float4*>(cp + 4) = r1;
    }
}

/* ---------------- windowed attention: block per (window, head) ----------- */
__global__ void __launch_bounds__(256)
attn_kernel(const float* __restrict__ qkv, const float* __restrict__ rpb,
            float* __restrict__ out)
{
    __shared__ float qT[HD][WINSZ + 1];    /* transposed: conflict-free col reads */
    __shared__ float kT[HD][WINSZ + 1];
    __shared__ float vs[WINSZ][HD + 4];
    __shared__ float Ss[WINSZ][WINSZ + 1];
    __shared__ float bs[2 * WINSZ - 1];

    const int w = blockIdx.x, h = blockIdx.y;
    const int tid = threadIdx.x;

    if (tid < 2 * WINSZ - 1) bs[tid] = rpb[tid * HEADS + h];

    const float* base = qkv + (size_t)w * WINSZ * (3 * DIMC) + h * HD;
    for (int e = tid; e < WINSZ * HD / 4; e += 256) {  /* 512 float4 per matrix */
        int tok = e >> 3;
        int d4  = (e & 7) << 2;
        const float* p = base + (size_t)tok * (3 * DIMC) + d4;
        float4 q4 = *reinterpret_cast<const float4*>(p);
        float4 k4 = *reinterpret_cast<const float4*>(p + DIMC);
        float4 v4 = *reinterpret_cast<const float4*>(p + 2 * DIMC);
        qT[d4 + 0][tok] = q4.x; qT[d4 + 1][tok] = q4.y;
        qT[d4 + 2][tok] = q4.z; qT[d4 + 3][tok] = q4.w;
        kT[d4 + 0][tok] = k4.x; kT[d4 + 1][tok] = k4.y;
        kT[d4 + 2][tok] = k4.z; kT[d4 + 3][tok] = k4.w;
        *reinterpret_cast<float4*>(&vs[tok][d4]) = v4;
    }
    __syncthreads();

    /* S = scale * q k^T + bias : each thread computes a 4x4 subtile */
    {
        const int ti = (tid >> 4) << 2;
        const int tj = (tid & 15) << 2;
        float s[4][4];
#pragma unroll
        for (int a = 0; a < 4; a++)
#pragma unroll
            for (int b = 0; b < 4; b++) s[a][b] = 0.f;
#pragma unroll 8
        for (int d = 0; d < HD; d++) {
            float qa[4], kb[4];
#pragma unroll
            for (int a = 0; a < 4; a++) qa[a] = qT[d][ti + a];
#pragma unroll
            for (int b = 0; b < 4; b++) kb[b] = kT[d][tj + b];
#pragma unroll
            for (int a = 0; a < 4; a++)
#pragma unroll
                for (int b = 0; b < 4; b++) s[a][b] += qa[a] * kb[b];
        }
        const float scale = 0.17677669529663687f;  /* 1/sqrt(32) */
#pragma unroll
        for (int a = 0; a < 4; a++)
#pragma unroll
            for (int b = 0; b < 4; b++)
                Ss[ti + a][tj + b] =
                    s[a][b] * scale + bs[(ti + a) - (tj + b) + WINSZ - 1];
    }
    __syncthreads();

    /* row softmax: warp handles 8 rows, 2 cols per lane */
    {
        const int wid = tid >> 5, lane = tid & 31;
#pragma unroll
        for (int rr = 0; rr < 8; rr++) {
            int i = wid * 8 + rr;
            float a0 = Ss[i][lane], a1 = Ss[i][lane + 32];
            float mx = fmaxf(a0, a1);
#pragma unroll
            for (int o = 16; o > 0; o >>= 1)
                mx = fmaxf(mx, __shfl_xor_sync(0xffffffffu, mx, o));
            float e0 = __expf(a0 - mx), e1 = __expf(a1 - mx);
            float sm = e0 + e1;
#pragma unroll
            for (int o = 16; o > 0; o >>= 1)
                sm += __shfl_xor_sync(0xffffffffu, sm, o);
            float inv = 1.0f / sm;
            Ss[i][lane] = e0 * inv;
            Ss[i][lane + 32] = e1 * inv;
        }
    }
    __syncthreads();

    /* out = P @ V : warp-uniform row i, lane = head dim -> conflict-free.
       4 independent partial accumulators break the serial FFMA chain. */
    for (int e = tid; e < WINSZ * HD; e += 256) {
        int i = e >> 5, d = e & 31;
        float a0 = 0.f, a1 = 0.f, a2 = 0.f, a3 = 0.f;
#pragma unroll
        for (int j = 0; j < WINSZ; j += 4) {
            a0 += Ss[i][j + 0] * vs[j + 0][d];
            a1 += Ss[i][j + 1] * vs[j + 1][d];
            a2 += Ss[i][j + 2] * vs[j + 2][d];
            a3 += Ss[i][j + 3] * vs[j + 3][d];
        }
        out[(size_t)(w * WINSZ + i) * DIMC + h * HD + d] = (a0 + a1) + (a2 + a3);
    }
}

/* x1[b, 0:SHIFT] = x[b, 0:SHIFT] (rolled-in head rows: residual only) */
__global__ void head_copy(const float* __restrict__ x, float* __restrict__ x1)
{
    int idx = blockIdx.x * blockDim.x + threadIdx.x;
    const int per = SHIFTN * DIMC / 4;          /* 2048 float4 per batch */
    if (idx >= BATCH * per) return;
    int bb = idx / per, off = idx - bb * per;
    size_t base4 = (size_t)bb * SEQ * (DIMC / 4) + off;
    reinterpret_cast<float4*>(x1)[base4] =
        reinterpret_cast<const float4*>(x)[base4];
}

/* ---------------- host driver ------------------------------------------- */
extern "C" void kernel_launch(void* const* d_in, const int* in_sizes, int n_in,
                              void* d_out, int out_size)
{
    const float* x      = (const float*)d_in[0];
    const float* g1     = (const float*)d_in[1];
    const float* b1     = (const float*)d_in[2];
    const float* qkv_w  = (const float*)d_in[3];
    const float* qkv_b  = (const float*)d_in[4];
    const float* rpb    = (const float*)d_in[5];
    const float* proj_w = (const float*)d_in[6];
    const float* proj_b = (const float*)d_in[7];
    const float* g2     = (const float*)d_in[8];
    const float* b2     = (const float*)d_in[9];
    const float* fc1_w  = (const float*)d_in[10];
    const float* fc1_b  = (const float*)d_in[11];
    const float* fc2_w  = (const float*)d_in[12];
    const float* fc2_b  = (const float*)d_in[13];
    float* out = (float*)d_out;

    float *shifted, *qkvb, *attnb, *x1, *hn, *hidden;
    cudaGetSymbolAddress((void**)&shifted, g_shifted);
    cudaGetSymbolAddress((void**)&qkvb,    g_qkv);
    cudaGetSymbolAddress((void**)&attnb,   g_attn);
    cudaGetSymbolAddress((void**)&x1,      g_x1);
    cudaGetSymbolAddress((void**)&hn,      g_hn);
    cudaGetSymbolAddress((void**)&hidden,  g_hidden);

    /* LN1 + shift + window layout (windows are contiguous 64-token runs) */
    ln_kernel<<<NTOK / 8, 256>>>(x, g1, b1, shifted, 1);

    /* QKV: (131072,256) @ (256,768) */
    gemm_kernel<0><<<dim3((3 * DIMC) / BN, NTOK / BM), 256>>>(
        shifted, qkv_w, qkv_b, qkvb, nullptr, 3 * DIMC, DIMC);

    /* windowed attention */
    attn_kernel<<<dim3(NWIN, HEADS), 256>>>(qkvb, rpb, attnb);

    /* proj + unshift + residual into x1 */
    gemm_kernel<2><<<dim3(DIMC / BN, NTOK / BM), 256>>>(
        attnb, proj_w, proj_b, x1, x, DIMC, DIMC);
    head_copy<<<(BATCH * SHIFTN * DIMC / 4 + 255) / 256, 256>>>(x, x1);

    /* LN2 */
    ln_kernel<<<NTOK / 8, 256>>>(x1, g2, b2, hn, 0);

    /* FC1 + exact GELU: (131072,256) @ (256,1024) */
    gemm_kernel<1><<<dim3(HIDDEN / BN, NTOK / BM), 256>>>(
        hn, fc1_w, fc1_b, hidden, nullptr, HIDDEN, DIMC);

    /* FC2 + residual -> out: (131072,1024) @ (1024,256) */
    gemm_kernel<3><<<dim3(DIMC / BN, NTOK / BM), 256>>>(
        hidden, fc2_w, fc2_b, out, x1, DIMC, HIDDEN);
}

// round 15
// speedup vs baseline: 1.0975x; 1.0975x over previous
#include <cuda_runtime.h>
#include <math.h>

#define DIMC   256
#define HEADS  8
#define HD     32
#define WINSZ  64
#define SHIFTN 32
#define HIDDEN 1024
#define BATCH  8
#define SEQ    16384
#define NTOK   (BATCH*SEQ)      /* 131072 */
#define NWIN   (NTOK/WINSZ)     /* 2048 */

/* ---------------- scratch (device globals: allocation-free) -------------- */
__device__ float g_shifted[NTOK*DIMC];
__device__ float g_qkv   [NTOK*3*DIMC];
__device__ float g_attn  [NTOK*DIMC];
__device__ float g_x1    [NTOK*DIMC];
__device__ float g_hn    [NTOK*DIMC];
__device__ float g_hidden[NTOK*HIDDEN];

/* ---------------- packed f32x2 helpers (sm_103a FFMA2) ------------------- */
__device__ __forceinline__ void ffma2(unsigned long long& d,
                                      unsigned long long a,
                                      unsigned long long b) {
    asm("fma.rn.f32x2 %0, %1, %2, %3;" : "=l"(d) : "l"(a), "l"(b), "l"(d));
}
__device__ __forceinline__ void unpack2(unsigned long long v, float& lo, float& hi) {
    asm("mov.b64 {%0, %1}, %2;" : "=f"(lo), "=f"(hi) : "l"(v));
}

/* ---------------- LayerNorm (warp per 256-float row) --------------------- */
/* shifted=1: out[row] = LN(x[row+SHIFT]) for ls < SEQ-SHIFT else 0 (fused shift) */
__global__ void ln_kernel(const float* __restrict__ xin, const float* __restrict__ g,
                          const float* __restrict__ b, float* __restrict__ out, int shifted)
{
    int gw   = (blockIdx.x * blockDim.x + threadIdx.x) >> 5;
    int lane = threadIdx.x & 31;
    if (gw >= NTOK) return;

    float4* o4 = reinterpret_cast<float4*>(out + (size_t)gw * DIMC);
    const float* src;
    if (shifted) {
        int ls = gw & (SEQ - 1);
        if (ls >= SEQ - SHIFTN) {
            float4 z = make_float4(0.f, 0.f, 0.f, 0.f);
            o4[lane] = z; o4[lane + 32] = z;
            return;
        }
        src = xin + ((size_t)gw + SHIFTN) * DIMC;   /* same batch: ls+SHIFT < SEQ */
    } else {
        src = xin + (size_t)gw * DIMC;
    }

    const float4* x4 = reinterpret_cast<const float4*>(src);
    float4 v0 = x4[lane], v1 = x4[lane + 32];
    float s  = v0.x + v0.y + v0.z + v0.w + v1.x + v1.y + v1.z + v1.w;
    float sq = v0.x*v0.x + v0.y*v0.y + v0.z*v0.z + v0.w*v0.w
             + v1.x*v1.x + v1.y*v1.y + v1.z*v1.z + v1.w*v1.w;
#pragma unroll
    for (int o = 16; o > 0; o >>= 1) {
        s  += __shfl_xor_sync(0xffffffffu, s,  o);
        sq += __shfl_xor_sync(0xffffffffu, sq, o);
    }
    float mu  = s * (1.0f / DIMC);
    float var = sq * (1.0f / DIMC) - mu * mu;
    float inv = rsqrtf(var + 1e-5f);

    const float4* g4 = reinterpret_cast<const float4*>(g);
    const float4* b4 = reinterpret_cast<const float4*>(b);
    float4 ga = g4[lane], gb = g4[lane + 32];
    float4 ba = b4[lane], bb = b4[lane + 32];
    float4 r0, r1;
    r0.x = (v0.x - mu) * inv * ga.x + ba.x;
    r0.y = (v0.y - mu) * inv * ga.y + ba.y;
    r0.z = (v0.z - mu) * inv * ga.z + ba.z;
    r0.w = (v0.w - mu) * inv * ga.w + ba.w;
    r1.x = (v1.x - mu) * inv * gb.x + bb.x;
    r1.y = (v1.y - mu) * inv * gb.y + bb.y;
    r1.z = (v1.z - mu) * inv * gb.z + bb.z;
    r1.w = (v1.w - mu) * inv * gb.w + bb.w;
    o4[lane] = r0; o4[lane + 32] = r1;
}

/* ------- 128x128x8 SGEMM, 8x8 microtile via f32x2 FFMA2, dbl-buffered ----
   __launch_bounds__(256, 2): cap regs at 128 so 2 CTAs/SM co-reside
   (R10 ncu: 148 regs -> 1 CTA/SM -> occ 12.4% -> fma pipe only 41%).
   A tile stored PRE-DUPLICATED as float2 (a,a); B pairs read directly from
   shared as 64-bit packed operands. Inner loop: 6 LDS.128 + 32 FFMA2, 0 MOVs.
   C[M,N] = A[M,K] @ B[K,N] + bias ; MODE: 0 plain, 1 +GELU(exact),
   2 proj: write C[(m+SHIFT)] = resid[(m+SHIFT)] + y (skip tail rows),
   3 +resid[m] */
#define BM 128
#define BN 128
#define BK 8

template <int MODE>
__global__ void __launch_bounds__(256, 2)
gemm_kernel(const float* __restrict__ A, const float* __restrict__ Bw,
            const float* __restrict__ bias, float* __restrict__ C,
            const float* __restrict__ resid, int Ncols, int K)
{
    __shared__ float2 As2[2][BK][BM];     /* duplicated pairs: 8KB per buffer */
    __shared__ float  Bs [2][BK][BN];     /* 4KB per buffer */

    const int tid = threadIdx.x;
    const int m0 = blockIdx.y * BM;
    const int n0 = blockIdx.x * BN;
    const int tx = tid & 15;          /* 0..15 : column group */
    const int ty = tid >> 4;          /* 0..15 : row group    */

    /* global-load mapping: one float4 of A, one float4 of B per thread */
    const int a_row = tid >> 1;              /* 0..127 */
    const int a_kc  = (tid & 1) << 2;        /* 0 or 4 */
    const int b_row = tid >> 5;              /* 0..7   */
    const int b_col = (tid & 31) << 2;       /* 0..124 */

    const float* Ap = A + (size_t)(m0 + a_row) * K + a_kc;
    const float* Bp = Bw + (size_t)b_row * Ncols + n0 + b_col;

    /* acc2[i][j2] packs columns (2*j2, 2*j2+1) for row i */
    unsigned long long acc2[8][4];
#pragma unroll
    for (int i = 0; i < 8; i++)
#pragma unroll
        for (int j = 0; j < 4; j++) acc2[i][j] = 0ull;

    /* prologue: load first K-slab */
    float4 a_reg = *reinterpret_cast<const float4*>(Ap);
    float4 b_reg = *reinterpret_cast<const float4*>(Bp);
    As2[0][a_kc + 0][a_row] = make_float2(a_reg.x, a_reg.x);
    As2[0][a_kc + 1][a_row] = make_float2(a_reg.y, a_reg.y);
    As2[0][a_kc + 2][a_row] = make_float2(a_reg.z, a_reg.z);
    As2[0][a_kc + 3][a_row] = make_float2(a_reg.w, a_reg.w);
    *reinterpret_cast<float4*>(&Bs[0][b_row][b_col]) = b_reg;
    __syncthreads();

    int buf = 0;
    for (int k0 = BK; k0 < K; k0 += BK) {
        /* prefetch next slab into registers (overlaps with math below) */
        a_reg = *reinterpret_cast<const float4*>(Ap + k0);
        b_reg = *reinterpret_cast<const float4*>(Bp + (size_t)k0 * Ncols);

#pragma unroll
        for (int k = 0; k < BK; k++) {
            const unsigned long long* ap =
                reinterpret_cast<const unsigned long long*>(&As2[buf][k][ty * 8]);
            const unsigned long long* bq =
                reinterpret_cast<const unsigned long long*>(&Bs[buf][k][tx * 8]);
            unsigned long long bp0 = bq[0], bp1 = bq[1], bp2 = bq[2], bp3 = bq[3];
#pragma unroll
            for (int i = 0; i < 8; i++) {
                unsigned long long ad = ap[i];
                ffma2(acc2[i][0], ad, bp0);
                ffma2(acc2[i][1], ad, bp1);
                ffma2(acc2[i][2], ad, bp2);
                ffma2(acc2[i][3], ad, bp3);
            }
        }

        /* commit prefetched slab to the other buffer */
        int nb = buf ^ 1;
        As2[nb][a_kc + 0][a_row] = make_float2(a_reg.x, a_reg.x);
        As2[nb][a_kc + 1][a_row] = make_float2(a_reg.y, a_reg.y);
        As2[nb][a_kc + 2][a_row] = make_float2(a_reg.z, a_reg.z);
        As2[nb][a_kc + 3][a_row] = make_float2(a_reg.w, a_reg.w);
        *reinterpret_cast<float4*>(&Bs[nb][b_row][b_col]) = b_reg;
        __syncthreads();
        buf = nb;
    }

    /* final slab */
#pragma unroll
    for (int k = 0; k < BK; k++) {
        const unsigned long long* ap =
            reinterpret_cast<const unsigned long long*>(&As2[buf][k][ty * 8]);
        const unsigned long long* bq =
            reinterpret_cast<const unsigned long long*>(&Bs[buf][k][tx * 8]);
        unsigned long long bp0 = bq[0], bp1 = bq[1], bp2 = bq[2], bp3 = bq[3];
#pragma unroll
        for (int i = 0; i < 8; i++) {
            unsigned long long ad = ap[i];
            ffma2(acc2[i][0], ad, bp0);
            ffma2(acc2[i][1], ad, bp1);
            ffma2(acc2[i][2], ad, bp2);
            ffma2(acc2[i][3], ad, bp3);
        }
    }

    /* unpack to scalar grid */
    float acc[8][8];
#pragma unroll
    for (int i = 0; i < 8; i++)
#pragma unroll
        for (int j2 = 0; j2 < 4; j2++)
            unpack2(acc2[i][j2], acc[i][2 * j2], acc[i][2 * j2 + 1]);

    /* ------------- epilogue ------------- */
    const int n = n0 + tx * 8;
    float4 bv0 = *reinterpret_cast<const float4*>(&bias[n]);
    float4 bv1 = *reinterpret_cast<const float4*>(&bias[n + 4]);
#pragma unroll
    for (int i = 0; i < 8; i++) {
        int m = m0 + ty * 8 + i;
        float4 r0, r1;
        r0.x = acc[i][0] + bv0.x; r0.y = acc[i][1] + bv0.y;
        r0.z = acc[i][2] + bv0.z; r0.w = acc[i][3] + bv0.w;
        r1.x = acc[i][4] + bv1.x; r1.y = acc[i][5] + bv1.y;
        r1.z = acc[i][6] + bv1.z; r1.w = acc[i][7] + bv1.w;
        if (MODE == 1) {
            const float c = 0.70710678118654752f;
            r0.x = 0.5f * r0.x * (1.0f + erff(r0.x * c));
            r0.y = 0.5f * r0.y * (1.0f + erff(r0.y * c));
            r0.z = 0.5f * r0.z * (1.0f + erff(r0.z * c));
            r0.w = 0.5f * r0.w * (1.0f + erff(r0.w * c));
            r1.x = 0.5f * r1.x * (1.0f + erff(r1.x * c));
            r1.y = 0.5f * r1.y * (1.0f + erff(r1.y * c));
            r1.z = 0.5f * r1.z * (1.0f + erff(r1.z * c));
            r1.w = 0.5f * r1.w * (1.0f + erff(r1.w * c));
        }
        if (MODE == 2) {
            int ls = m & (SEQ - 1);
            if (ls >= SEQ - SHIFTN) continue;   /* rolled-off rows discarded */
            int dst = m + SHIFTN;               /* same batch */
            const float* rp = &resid[(size_t)dst * Ncols + n];
            float4 rv0 = *reinterpret_cast<const float4*>(rp);
            float4 rv1 = *reinterpret_cast<const float4*>(rp + 4);
            r0.x += rv0.x; r0.y += rv0.y; r0.z += rv0.z; r0.w += rv0.w;
            r1.x += rv1.x; r1.y += rv1.y; r1.z += rv1.z; r1.w += rv1.w;
            float* cp = &C[(size_t)dst * Ncols + n];
            *reinterpret_cast<float4*>(cp) = r0;
            *reinterpret_cast<float4*>(cp + 4) = r1;
            continue;
        }
        if (MODE == 3) {
            const float* rp = &resid[(size_t)m * Ncols + n];
            float4 rv0 = *reinterpret_cast<const float4*>(rp);
            float4 rv1 = *reinterpret_cast<const float4*>(rp + 4);
            r0.x += rv0.x; r0.y += rv0.y; r0.z += rv0.z; r0.w += rv0.w;
            r1.x += rv1.x; r1.y += rv1.y; r1.z += rv1.z; r1.w += rv1.w;
        }
        float* cp = &C[(size_t)m * Ncols + n];
        *reinterpret_cast<float4*>(cp) = r0;
        *reinterpret_cast<float4*>(cp + 4) = r1;
    }
}

/* ---------------- windowed attention: block per (window, head) ----------- */
__global__ void __launch_bounds__(256)
attn_kernel(const float* __restrict__ qkv, const float* __restrict__ rpb,
            float* __restrict__ out)
{
    __shared__ float qT[HD][WINSZ + 1];    /* transposed: conflict-free col reads */
    __shared__ float kT[HD][WINSZ + 1];
    __shared__ float vs[WINSZ][HD + 4];
    __shared__ float Ss[WINSZ][WINSZ + 1];
    __shared__ float bs[2 * WINSZ - 1];

    const int w = blockIdx.x, h = blockIdx.y;
    const int tid = threadIdx.x;

    if (tid < 2 * WINSZ - 1) bs[tid] = rpb[tid * HEADS + h];

    const float* base = qkv + (size_t)w * WINSZ * (3 * DIMC) + h * HD;
    for (int e = tid; e < WINSZ * HD / 4; e += 256) {  /* 512 float4 per matrix */
        int tok = e >> 3;
        int d4  = (e & 7) << 2;
        const float* p = base + (size_t)tok * (3 * DIMC) + d4;
        float4 q4 = *reinterpret_cast<const float4*>(p);
        float4 k4 = *reinterpret_cast<const float4*>(p + DIMC);
        float4 v4 = *reinterpret_cast<const float4*>(p + 2 * DIMC);
        qT[d4 + 0][tok] = q4.x; qT[d4 + 1][tok] = q4.y;
        qT[d4 + 2][tok] = q4.z; qT[d4 + 3][tok] = q4.w;
        kT[d4 + 0][tok] = k4.x; kT[d4 + 1][tok] = k4.y;
        kT[d4 + 2][tok] = k4.z; kT[d4 + 3][tok] = k4.w;
        *reinterpret_cast<float4*>(&vs[tok][d4]) = v4;
    }
    __syncthreads();

    /* S = scale * q k^T + bias : each thread computes a 4x4 subtile */
    {
        const int ti = (tid >> 4) << 2;
        const int tj = (tid & 15) << 2;
        float s[4][4];
#pragma unroll
        for (int a = 0; a < 4; a++)
#pragma unroll
            for (int b = 0; b < 4; b++) s[a][b] = 0.f;
#pragma unroll 8
        for (int d = 0; d < HD; d++) {
            float qa[4], kb[4];
#pragma unroll
            for (int a = 0; a < 4; a++) qa[a] = qT[d][ti + a];
#pragma unroll
            for (int b = 0; b < 4; b++) kb[b] = kT[d][tj + b];
#pragma unroll
            for (int a = 0; a < 4; a++)
#pragma unroll
                for (int b = 0; b < 4; b++) s[a][b] += qa[a] * kb[b];
        }
        const float scale = 0.17677669529663687f;  /* 1/sqrt(32) */
#pragma unroll
        for (int a = 0; a < 4; a++)
#pragma unroll
            for (int b = 0; b < 4; b++)
                Ss[ti + a][tj + b] =
                    s[a][b] * scale + bs[(ti + a) - (tj + b) + WINSZ - 1];
    }
    __syncthreads();

    /* row softmax: warp handles 8 rows, 2 cols per lane */
    {
        const int wid = tid >> 5, lane = tid & 31;
#pragma unroll
        for (int rr = 0; rr < 8; rr++) {
            int i = wid * 8 + rr;
            float a0 = Ss[i][lane], a1 = Ss[i][lane + 32];
            float mx = fmaxf(a0, a1);
#pragma unroll
            for (int o = 16; o > 0; o >>= 1)
                mx = fmaxf(mx, __shfl_xor_sync(0xffffffffu, mx, o));
            float e0 = __expf(a0 - mx), e1 = __expf(a1 - mx);
            float sm = e0 + e1;
#pragma unroll
            for (int o = 16; o > 0; o >>= 1)
                sm += __shfl_xor_sync(0xffffffffu, sm, o);
            float inv = 1.0f / sm;
            Ss[i][lane] = e0 * inv;
            Ss[i][lane + 32] = e1 * inv;
        }
    }
    __syncthreads();

    /* out = P @ V : warp-uniform row i, lane = head dim -> conflict-free.
       4 independent partial accumulators break the serial FFMA chain. */
    for (int e = tid; e < WINSZ * HD; e += 256) {
        int i = e >> 5, d = e & 31;
        float a0 = 0.f, a1 = 0.f, a2 = 0.f, a3 = 0.f;
#pragma unroll
        for (int j = 0; j < WINSZ; j += 4) {
            a0 += Ss[i][j + 0] * vs[j + 0][d];
            a1 += Ss[i][j + 1] * vs[j + 1][d];
            a2 += Ss[i][j + 2] * vs[j + 2][d];
            a3 += Ss[i][j + 3] * vs[j + 3][d];
        }
        out[(size_t)(w * WINSZ + i) * DIMC + h * HD + d] = (a0 + a1) + (a2 + a3);
    }
}

/* x1[b, 0:SHIFT] = x[b, 0:SHIFT] (rolled-in head rows: residual only) */
__global__ void head_copy(const float* __restrict__ x, float* __restrict__ x1)
{
    int idx = blockIdx.x * blockDim.x + threadIdx.x;
    const int per = SHIFTN * DIMC / 4;          /* 2048 float4 per batch */
    if (idx >= BATCH * per) return;
    int bb = idx / per, off = idx - bb * per;
    size_t base4 = (size_t)bb * SEQ * (DIMC / 4) + off;
    reinterpret_cast<float4*>(x1)[base4] =
        reinterpret_cast<const float4*>(x)[base4];
}

/* ---------------- host driver ------------------------------------------- */
extern "C" void kernel_launch(void* const* d_in, const int* in_sizes, int n_in,
                              void* d_out, int out_size)
{
    const float* x      = (const float*)d_in[0];
    const float* g1     = (const float*)d_in[1];
    const float* b1     = (const float*)d_in[2];
    const float* qkv_w  = (const float*)d_in[3];
    const float* qkv_b  = (const float*)d_in[4];
    const float* rpb    = (const float*)d_in[5];
    const float* proj_w = (const float*)d_in[6];
    const float* proj_b = (const float*)d_in[7];
    const float* g2     = (const float*)d_in[8];
    const float* b2     = (const float*)d_in[9];
    const float* fc1_w  = (const float*)d_in[10];
    const float* fc1_b  = (const float*)d_in[11];
    const float* fc2_w  = (const float*)d_in[12];
    const float* fc2_b  = (const float*)d_in[13];
    float* out = (float*)d_out;

    float *shifted, *qkvb, *attnb, *x1, *hn, *hidden;
    cudaGetSymbolAddress((void**)&shifted, g_shifted);
    cudaGetSymbolAddress((void**)&qkvb,    g_qkv);
    cudaGetSymbolAddress((void**)&attnb,   g_attn);
    cudaGetSymbolAddress((void**)&x1,      g_x1);
    cudaGetSymbolAddress((void**)&hn,      g_hn);
    cudaGetSymbolAddress((void**)&hidden,  g_hidden);

    /* LN1 + shift + window layout (windows are contiguous 64-token runs) */
    ln_kernel<<<NTOK / 8, 256>>>(x, g1, b1, shifted, 1);

    /* QKV: (131072,256) @ (256,768) */
    gemm_kernel<0><<<dim3((3 * DIMC) / BN, NTOK / BM), 256>>>(
        shifted, qkv_w, qkv_b, qkvb, nullptr, 3 * DIMC, DIMC);

    /* windowed attention */
    attn_kernel<<<dim3(NWIN, HEADS), 256>>>(qkvb, rpb, attnb);

    /* proj + unshift + residual into x1 */
    gemm_kernel<2><<<dim3(DIMC / BN, NTOK / BM), 256>>>(
        attnb, proj_w, proj_b, x1, x, DIMC, DIMC);
    head_copy<<<(BATCH * SHIFTN * DIMC / 4 + 255) / 256, 256>>>(x, x1);

    /* LN2 */
    ln_kernel<<<NTOK / 8, 256>>>(x1, g2, b2, hn, 0);

    /* FC1 + exact GELU: (131072,256) @ (256,1024) */
    gemm_kernel<1><<<dim3(HIDDEN / BN, NTOK / BM), 256>>>(
        hn, fc1_w, fc1_b, hidden, nullptr, HIDDEN, DIMC);

    /* FC2 + residual -> out: (131072,1024) @ (1024,256) */
    gemm_kernel<3><<<dim3(DIMC / BN, NTOK / BM), 256>>>(
        hidden, fc2_w, fc2_b, out, x1, DIMC, HIDDEN);
}